// round 4
// baseline (speedup 1.0000x reference)
#include <cuda_runtime.h>

#define DIM 85
#define B_ROWS 262144
#define THREADS 256
#define NBLOCKS 888                 // 148 SMs * 6 blocks (RF-bound residency)
#define WARPS_TOTAL (NBLOCKS * THREADS / 32)          // 7104
#define ROWS_PER_WARP ((B_ROWS + WARPS_TOTAL - 1) / WARPS_TOTAL)  // 37

__device__ float g_partials[NBLOCKS];
__device__ int   g_count = 0;

__global__ __launch_bounds__(THREADS)
void qfd_warp(const float* __restrict__ in, const float* __restrict__ tg,
              float* __restrict__ out)
{
    __shared__ float warp_part[THREADS / 32];
    __shared__ bool  s_is_last;

    const unsigned FULL = 0xffffffffu;
    const int lane = threadIdx.x & 31;
    const int gwarp = (blockIdx.x * THREADS + threadIdx.x) >> 5;
    const int row0 = gwarp * ROWS_PER_WARP;

    // lane element indices (blocked layout: lane l -> 3l, 3l+1, 3l+2)
    const int k0 = 3 * lane;
    const bool v0 = (k0     < DIM);
    const bool v1 = (k0 + 1 < DIM);
    const bool v2 = (k0 + 2 < DIM);
    const float f0 = (float)k0, f1 = (float)(k0 + 1), f2 = (float)(k0 + 2);

    float accU  = 0.0f;   // sum over rows of per-lane U partials
    float accS2 = 0.0f;   // lane 31 only: sum of S^2

#pragma unroll 2
    for (int r = 0; r < ROWS_PER_WARP; r++) {
        int row = row0 + r;
        if (row < B_ROWS) {                       // uniform across warp
            const float* pi = in + (size_t)row * DIM + k0;
            const float* pt = tg + (size_t)row * DIM + k0;
            float d0 = v0 ? fabsf(pi[0] - pt[0]) : 0.0f;
            float d1 = v1 ? fabsf(pi[1] - pt[1]) : 0.0f;
            float d2 = v2 ? fabsf(pi[2] - pt[2]) : 0.0f;

            float t0 = f0 * d0, t1 = f1 * d1, t2 = f2 * d2;
            float sd = d0 + d1 + d2;              // lane-local sums
            float st = t0 + t1 + t2;

            // inclusive warp scans of sd (P) and st (T) — independent chains
            float Pi = sd, Ti = st;
#pragma unroll
            for (int o = 1; o < 32; o <<= 1) {
                float xp = __shfl_up_sync(FULL, Pi, o);
                float xt = __shfl_up_sync(FULL, Ti, o);
                if (lane >= o) { Pi += xp; Ti += xt; }
            }
            float Pex = Pi - sd;                  // exclusive prefixes
            float Tex = Ti - st;

            // U partial: sum_j d_j * (j*P_{<j} - T_{<j}) over this lane's elems
            float u = d0 * fmaf(f0, Pex, -Tex);
            float P = Pex + d0, T = Tex + t0;
            u = fmaf(d1, fmaf(f1, P, -T), u);
            P += d1; T += t1;
            u = fmaf(d2, fmaf(f2, P, -T), u);
            accU += u;

            if (lane == 31)                       // Pi at lane31 == row sum S
                accS2 = fmaf(Pi, Pi, accS2);
        }
    }

    // butterfly reduce accU and accS2 across the warp (fixed order)
#pragma unroll
    for (int o = 16; o; o >>= 1) {
        accU  += __shfl_xor_sync(FULL, accU,  o);
        accS2 += __shfl_xor_sync(FULL, accS2, o);
    }
    if (lane == 0)
        warp_part[(threadIdx.x >> 5)] = fmaf(-(2.0f / (float)DIM), accU, accS2);
    __syncthreads();

    if (threadIdx.x == 0) {
        float t = 0.0f;
#pragma unroll
        for (int i = 0; i < THREADS / 32; i++)
            t += warp_part[i];
        g_partials[blockIdx.x] = t;
        __threadfence();
        int old = atomicAdd(&g_count, 1);
        s_is_last = (old == NBLOCKS - 1);
    }
    __syncthreads();

    // last-arriving block: deterministic final reduce over NBLOCKS partials
    if (s_is_last) {
        __shared__ double sd[THREADS];
        double acc = 0.0;
#pragma unroll
        for (int j = 0; j < (NBLOCKS + THREADS - 1) / THREADS; j++) {
            int i = threadIdx.x + j * THREADS;
            if (i < NBLOCKS) acc += (double)g_partials[i];
        }
        sd[threadIdx.x] = acc;
        __syncthreads();
        for (int o = THREADS / 2; o; o >>= 1) {
            if (threadIdx.x < o) sd[threadIdx.x] += sd[threadIdx.x + o];
            __syncthreads();
        }
        if (threadIdx.x == 0) {
            out[0] = (float)(0.1 * sd[0]);
            g_count = 0;                          // reset for next graph replay
        }
    }
}

extern "C" void kernel_launch(void* const* d_in, const int* in_sizes, int n_in,
                              void* d_out, int out_size)
{
    const float* in = (const float*)d_in[0];
    const float* tg = (const float*)d_in[1];
    float* out = (float*)d_out;

    qfd_warp<<<NBLOCKS, THREADS>>>(in, tg, out);
}

// round 5
// speedup vs baseline: 1.0775x; 1.0775x over previous
#include <cuda_runtime.h>

#define DIM 85
#define B_ROWS 262144
#define ROWS 64                    // rows per block tile
#define THREADS 256
#define NBLOCKS (B_ROWS / ROWS)    // 4096
#define N4 (ROWS * DIM / 4)        // 1360 float4 per tile
#define LOAD_ITERS ((N4 + THREADS - 1) / THREADS)   // 6 (last predicated)

__device__ float g_partials[NBLOCKS];
__device__ int   g_count = 0;      // self-resetting arrival counter

__global__ __launch_bounds__(THREADS)
void qfd_fused(const float* __restrict__ in, const float* __restrict__ tg,
               float* __restrict__ out)
{
    __shared__ float s[ROWS * DIM];          // 21760 B; stride-85 scan conflict-free
    __shared__ float warp_part[2];           // partials from the 2 scanning warps
    __shared__ bool  s_is_last;

    const size_t base = (size_t)blockIdx.x * (ROWS * DIM);

    // ---- Tile load: all 256 threads, fully unrolled, front-batched LDG.128 ----
    {
        const float4* __restrict__ in4 = (const float4*)(in + base);
        const float4* __restrict__ tg4 = (const float4*)(tg + base);
        float4* s4 = (float4*)s;
#pragma unroll
        for (int j = 0; j < LOAD_ITERS; j++) {
            int i = threadIdx.x + j * THREADS;
            if (i < N4) {
                float4 a = in4[i];
                float4 b = tg4[i];
                float4 d;
                d.x = fabsf(a.x - b.x);
                d.y = fabsf(a.y - b.y);
                d.z = fabsf(a.z - b.z);
                d.w = fabsf(a.w - b.w);
                s4[i] = d;
            }
        }
    }
    __syncthreads();

    // ---- Per-row O(D) Toeplitz scan (threads 0..63):  q = S^2 - (2/85)*U ----
    // U = sum_{i<j} (j-i) d_i d_j, via prefix sums P (of d) and Qn (of -k*d_k).
    if (threadIdx.x < ROWS) {
        const float* r = s + threadIdx.x * DIM;
        float P  = 0.0f;
        float Qn = 0.0f;
        float U  = 0.0f;
#pragma unroll
        for (int k = 0; k < DIM; k++) {
            float d = r[k];
            U  = fmaf(d, fmaf((float)k, P, Qn), U);
            P += d;
            Qn = fmaf(-(float)k, d, Qn);
        }
        float q = fmaf(P, P, -(2.0f / (float)DIM) * U);

        // warp-level deterministic reduce (2 scanning warps)
        for (int o = 16; o; o >>= 1)
            q += __shfl_down_sync(0xffffffffu, q, o);
        if ((threadIdx.x & 31) == 0)
            warp_part[threadIdx.x >> 5] = q;
    }
    __syncthreads();

    if (threadIdx.x == 0) {
        float t = warp_part[0] + warp_part[1];
        g_partials[blockIdx.x] = t;
        __threadfence();                          // partial visible before arrival
        int old = atomicAdd(&g_count, 1);
        s_is_last = (old == NBLOCKS - 1);
    }
    __syncthreads();

    // ---- Last-arriving block: final deterministic reduce ----
    if (s_is_last) {
        __shared__ double sd[THREADS];
        double acc = 0.0;
#pragma unroll
        for (int j = 0; j < NBLOCKS / THREADS; j++)     // 16 iterations, fixed order
            acc += (double)g_partials[threadIdx.x + j * THREADS];
        sd[threadIdx.x] = acc;
        __syncthreads();
        for (int o = THREADS / 2; o; o >>= 1) {
            if (threadIdx.x < o) sd[threadIdx.x] += sd[threadIdx.x + o];
            __syncthreads();
        }
        if (threadIdx.x == 0) {
            out[0] = (float)(0.1 * sd[0]);
            g_count = 0;                          // self-reset for next replay
        }
    }
}

extern "C" void kernel_launch(void* const* d_in, const int* in_sizes, int n_in,
                              void* d_out, int out_size)
{
    const float* in = (const float*)d_in[0];
    const float* tg = (const float*)d_in[1];
    float* out = (float*)d_out;

    qfd_fused<<<NBLOCKS, THREADS>>>(in, tg, out);
}

// round 6
// speedup vs baseline: 1.2505x; 1.1606x over previous
#include <cuda_runtime.h>

#define DIM 85
#define B_ROWS 262144
#define ROWS 128                   // rows per block tile
#define THREADS 256
#define NBLOCKS (B_ROWS / ROWS)    // 2048
#define N4 (ROWS * DIM / 4)        // 2720 float4 per tile
#define LOAD_ITERS ((N4 + THREADS - 1) / THREADS)   // 11 (last predicated)
#define H0 43                      // first-half length (k = 0..42)

__device__ float g_partials[NBLOCKS];
__device__ int   g_count = 0;      // self-resetting arrival counter

__global__ __launch_bounds__(THREADS)
void qfd_fused(const float* __restrict__ in, const float* __restrict__ tg,
               float* __restrict__ out)
{
    __shared__ float s[ROWS * DIM];          // 43520 B; stride-85 reads conflict-free
    __shared__ float sP[ROWS], sT[ROWS], sU[ROWS];   // second-half partials
    __shared__ float warp_part[4];
    __shared__ bool  s_is_last;

    const size_t base = (size_t)blockIdx.x * (ROWS * DIM);

    // ---- Tile load: 22 front-batched LDG.128 per thread (max MLP) ----
    {
        const float4* __restrict__ in4 = (const float4*)(in + base);
        const float4* __restrict__ tg4 = (const float4*)(tg + base);
        float4* s4 = (float4*)s;
#pragma unroll
        for (int j = 0; j < LOAD_ITERS; j++) {
            int i = threadIdx.x + j * THREADS;
            if (i < N4) {
                float4 a = in4[i];
                float4 b = tg4[i];
                float4 d;
                d.x = fabsf(a.x - b.x);
                d.y = fabsf(a.y - b.y);
                d.z = fabsf(a.z - b.z);
                d.w = fabsf(a.w - b.w);
                s4[i] = d;
            }
        }
    }
    __syncthreads();

    // ---- Split-row Toeplitz scan: all 256 threads, 43-step chains ----
    // Row q = S^2 - (2/85) * (U0 + U1 + P0*T1 - T0*P1),  S = P0 + P1
    // Each half: U_half = sum_{i<j in half} (j-i) d_i d_j  (absolute indices),
    //            P = sum d_k,  T = sum k*d_k.
    const int row  = threadIdx.x & (ROWS - 1);
    const bool hi  = threadIdx.x >= ROWS;      // second half of the row
    {
        const float* r = s + row * DIM + (hi ? H0 : 0);
        const int kbeg = hi ? H0 : 0;
        const int kcnt = hi ? (DIM - H0) : H0;
        float P = 0.0f, Tn = 0.0f, U = 0.0f;   // Tn = -T
#pragma unroll
        for (int k = 0; k < H0; k++) {
            if (k < kcnt) {
                float d  = r[k];
                float fk = (float)(k + kbeg);
                U  = fmaf(d, fmaf(fk, P, Tn), U);
                P += d;
                Tn = fmaf(-fk, d, Tn);
            }
        }
        if (hi) {
            sP[row] = P; sT[row] = -Tn; sU[row] = U;
        } else {
            // stash first-half results in registers; combine after barrier
            __syncthreads();
            float P1 = sP[row], T1 = sT[row], U1 = sU[row];
            float S  = P + P1;
            float U0 = U;
            // cross = P0*T1 - T0*P1  (T0 = -Tn)
            float cross = fmaf(P, T1, Tn * P1);
            float Utot  = U0 + U1 + cross;
            float q = fmaf(S, S, -(2.0f / (float)DIM) * Utot);

            for (int o = 16; o; o >>= 1)
                q += __shfl_down_sync(0xffffffffu, q, o);
            if ((threadIdx.x & 31) == 0)
                warp_part[threadIdx.x >> 5] = q;
        }
    }
    if (hi) __syncthreads();                   // matches the barrier in the !hi path
    __syncthreads();

    if (threadIdx.x == 0) {
        float t = warp_part[0] + warp_part[1] + warp_part[2] + warp_part[3];
        g_partials[blockIdx.x] = t;
        __threadfence();
        int old = atomicAdd(&g_count, 1);
        s_is_last = (old == NBLOCKS - 1);
    }
    __syncthreads();

    // ---- Last-arriving block: final deterministic reduce ----
    if (s_is_last) {
        __shared__ double sd[THREADS];
        double acc = 0.0;
#pragma unroll
        for (int j = 0; j < NBLOCKS / THREADS; j++)     // 8 iterations, fixed order
            acc += (double)g_partials[threadIdx.x + j * THREADS];
        sd[threadIdx.x] = acc;
        __syncthreads();
        for (int o = THREADS / 2; o; o >>= 1) {
            if (threadIdx.x < o) sd[threadIdx.x] += sd[threadIdx.x + o];
            __syncthreads();
        }
        if (threadIdx.x == 0) {
            out[0] = (float)(0.1 * sd[0]);
            g_count = 0;                       // self-reset for next replay
        }
    }
}

extern "C" void kernel_launch(void* const* d_in, const int* in_sizes, int n_in,
                              void* d_out, int out_size)
{
    const float* in = (const float*)d_in[0];
    const float* tg = (const float*)d_in[1];
    float* out = (float*)d_out;

    qfd_fused<<<NBLOCKS, THREADS>>>(in, tg, out);
}